// round 10
// baseline (speedup 1.0000x reference)
#include <cuda_runtime.h>
#include <cuda_bf16.h>
#include <math.h>
#include <stdint.h>

#define B_ 64
#define T_ 512
#define D_ 512
#define U_ 1024
#define G_ 4096   // 4*U

// ---------------------------------------------------------------------------
// Scratch (__device__ globals: allocation-free rule)
// ---------------------------------------------------------------------------
__device__ float         g_xz[(size_t)B_ * T_ * G_];     // fp32 input projections
__device__ __nv_bfloat16 g_xhi[(size_t)B_ * T_ * D_];    // x split
__device__ __nv_bfloat16 g_xlo[(size_t)B_ * T_ * D_];
__device__ __nv_bfloat16 g_Wt_hi[(size_t)G_ * D_];       // W^T split  [4096][512]
__device__ __nv_bfloat16 g_Wt_lo[(size_t)G_ * D_];
__device__ __nv_bfloat16 g_Rt_hi[(size_t)G_ * U_];       // R^T split  [4096][1024]
__device__ __nv_bfloat16 g_Rt_lo[(size_t)G_ * U_];
__device__ __nv_bfloat16 g_hhi[2][B_ * U_];              // h ping-pong, split
__device__ __nv_bfloat16 g_hlo[2][B_ * U_];
__device__ int           g_flags[T_ * 128];              // grid-barrier flags

// ---------------------------------------------------------------------------
// Helpers
// ---------------------------------------------------------------------------
__device__ __forceinline__ uint32_t smem_u32(const void* p) {
    uint32_t a;
    asm("{ .reg .u64 t; cvta.to.shared.u64 t, %1; cvt.u32.u64 %0, t; }" : "=r"(a) : "l"(p));
    return a;
}
__device__ __forceinline__ uint32_t sw128(uint32_t off) { return off ^ ((off >> 3) & 0x70); }
__device__ __forceinline__ uint32_t sw64 (uint32_t off) { return off ^ ((off >> 3) & 0x30); }

#define CP16(dst, src) \
    asm volatile("cp.async.cg.shared.global [%0], [%1], 16;" :: "r"(dst), "l"(src))
#define CP_COMMIT() asm volatile("cp.async.commit_group;" ::: "memory")
#define CP_WAIT2()  asm volatile("cp.async.wait_group 2;" ::: "memory")
#define CP_WAIT1()  asm volatile("cp.async.wait_group 1;" ::: "memory")
#define CP_WAIT0()  asm volatile("cp.async.wait_group 0;" ::: "memory")

__device__ __forceinline__ void ldsm_x4(uint32_t* r, uint32_t addr) {
    asm volatile("ldmatrix.sync.aligned.m8n8.x4.shared.b16 {%0,%1,%2,%3}, [%4];"
                 : "=r"(r[0]), "=r"(r[1]), "=r"(r[2]), "=r"(r[3]) : "r"(addr));
}
__device__ __forceinline__ void ldsm_x2(uint32_t* r, uint32_t addr) {
    asm volatile("ldmatrix.sync.aligned.m8n8.x2.shared.b16 {%0,%1}, [%2];"
                 : "=r"(r[0]), "=r"(r[1]) : "r"(addr));
}
__device__ __forceinline__ void mma16816(float* c, const uint32_t* a, const uint32_t* b) {
    asm volatile(
        "mma.sync.aligned.m16n8k16.row.col.f32.bf16.bf16.f32 "
        "{%0,%1,%2,%3}, {%4,%5,%6,%7}, {%8,%9}, {%0,%1,%2,%3};"
        : "+f"(c[0]), "+f"(c[1]), "+f"(c[2]), "+f"(c[3])
        : "r"(a[0]), "r"(a[1]), "r"(a[2]), "r"(a[3]), "r"(b[0]), "r"(b[1]));
}

// ---------------------------------------------------------------------------
// Prep kernels
// ---------------------------------------------------------------------------
__global__ void init_state()
{
    int i = blockIdx.x * blockDim.x + threadIdx.x;
    if (i < B_ * U_) {
        __nv_bfloat16 z = __float2bfloat16(0.0f);
        g_hhi[0][i] = z; g_hlo[0][i] = z;
        g_hhi[1][i] = z; g_hlo[1][i] = z;
    }
    if (i < T_ * 128) g_flags[i] = 0;
}

__global__ void split_x(const float* __restrict__ x)
{
    size_t i = (size_t)blockIdx.x * blockDim.x + threadIdx.x;
    size_t n4 = (size_t)B_ * T_ * D_ / 4;
    if (i >= n4) return;
    float4 v = ((const float4*)x)[i];
    float vv[4] = {v.x, v.y, v.z, v.w};
    __nv_bfloat162* ph = (__nv_bfloat162*)g_xhi;
    __nv_bfloat162* pl = (__nv_bfloat162*)g_xlo;
    __nv_bfloat16 h[4], l[4];
    #pragma unroll
    for (int j = 0; j < 4; j++) {
        h[j] = __float2bfloat16(vv[j]);
        l[j] = __float2bfloat16(vv[j] - __bfloat162float(h[j]));
    }
    ph[2*i]     = __halves2bfloat162(h[0], h[1]);
    ph[2*i + 1] = __halves2bfloat162(h[2], h[3]);
    pl[2*i]     = __halves2bfloat162(l[0], l[1]);
    pl[2*i + 1] = __halves2bfloat162(l[2], l[3]);
}

// src [rows][cols] fp32 -> Wt/Rt [cols][rows] bf16 hi/lo (device-resolved dst)
__global__ void transpose_split_sel(const float* __restrict__ src,
                                    int which, int rows, int cols)
{
    __nv_bfloat16* dhi = which ? g_Rt_hi : g_Wt_hi;
    __nv_bfloat16* dlo = which ? g_Rt_lo : g_Wt_lo;
    __shared__ float t[32][33];
    int x = blockIdx.x * 32 + threadIdx.x;
    int y0 = blockIdx.y * 32;
    #pragma unroll
    for (int i = 0; i < 32; i += 8)
        t[threadIdx.y + i][threadIdx.x] = src[(size_t)(y0 + threadIdx.y + i) * cols + x];
    __syncthreads();
    int ox = y0 + threadIdx.x;
    #pragma unroll
    for (int i = 0; i < 32; i += 8) {
        int orow = blockIdx.x * 32 + threadIdx.y + i;
        float v = t[threadIdx.x][threadIdx.y + i];
        __nv_bfloat16 h = __float2bfloat16(v);
        dhi[(size_t)orow * rows + ox] = h;
        dlo[(size_t)orow * rows + ox] = __float2bfloat16(v - __bfloat162float(h));
    }
}

// ---------------------------------------------------------------------------
// xz = x @ W + bias via mma.sync (3-term bf16 split) — unchanged from R7
// ---------------------------------------------------------------------------
#define XAHI 0
#define XALO 8192
#define XBHI 16384
#define XBLO 24576
#define XSTG 32768

__global__ __launch_bounds__(256) void gemm_xz_mma(const float* __restrict__ bias)
{
    extern __shared__ __align__(1024) char sm[];
    uint32_t smb = smem_u32(sm);
    const int tid  = threadIdx.x;
    const int wid  = tid >> 5;
    const int lane = tid & 31;
    const int m0 = blockIdx.y * 128;
    const int n0 = blockIdx.x * 128;

    const char* xh = (const char*)g_xhi;
    const char* xl = (const char*)g_xlo;
    const char* wh = (const char*)g_Wt_hi;
    const char* wl = (const char*)g_Wt_lo;

    float acc[2][8][4] = {};

    auto issue = [&](int kc, int s) {
        uint32_t st = smb + s * XSTG;
        #pragma unroll
        for (int i = 0; i < 2; i++) {
            int idx = tid + 256 * i;
            int r = idx >> 2, g = idx & 3;
            CP16(st + XAHI + sw64(r * 64 + g * 16),
                 xh + (size_t)(m0 + r) * 1024 + kc * 64 + g * 16);
        }
        #pragma unroll
        for (int i = 0; i < 2; i++) {
            int idx = tid + 256 * i;
            int r = idx >> 2, g = idx & 3;
            CP16(st + XALO + sw64(r * 64 + g * 16),
                 xl + (size_t)(m0 + r) * 1024 + kc * 64 + g * 16);
        }
        #pragma unroll
        for (int i = 0; i < 2; i++) {
            int idx = tid + 256 * i;
            int r = idx >> 2, g = idx & 3;
            CP16(st + XBHI + sw64(r * 64 + g * 16),
                 wh + (size_t)(n0 + r) * 1024 + kc * 64 + g * 16);
        }
        #pragma unroll
        for (int i = 0; i < 2; i++) {
            int idx = tid + 256 * i;
            int r = idx >> 2, g = idx & 3;
            CP16(st + XBLO + sw64(r * 64 + g * 16),
                 wl + (size_t)(n0 + r) * 1024 + kc * 64 + g * 16);
        }
    };

    issue(0, 0); CP_COMMIT();

    const int mrow = 32 * (wid >> 1);
    const int ncol = 64 * (wid & 1);
    const int mi  = lane >> 3;
    const int mr  = lane & 7;
    const int rr  = lane & 15;

    for (int kc = 0; kc < 16; kc++) {
        int s = kc & 1;
        if (kc + 1 < 16) { issue(kc + 1, s ^ 1); CP_COMMIT(); CP_WAIT1(); }
        else             { CP_WAIT0(); }
        __syncthreads();

        uint32_t st = smb + s * XSTG;
        #pragma unroll
        for (int ks = 0; ks < 2; ks++) {
            uint32_t ah[2][4], al[2][4];
            #pragma unroll
            for (int mf = 0; mf < 2; mf++) {
                int row = mrow + 16 * mf + ((mi & 1) << 3) + mr;
                uint32_t off = row * 64 + ks * 32 + ((mi >> 1) << 4);
                ldsm_x4(ah[mf], st + XAHI + sw64(off));
                ldsm_x4(al[mf], st + XALO + sw64(off));
            }
            #pragma unroll
            for (int nf = 0; nf < 8; nf++) {
                uint32_t bh[2], bl[2];
                int brow = ncol + 8 * nf + (rr & 7);
                uint32_t boff = brow * 64 + ks * 32 + ((rr >> 3) << 4);
                ldsm_x2(bh, st + XBHI + sw64(boff));
                ldsm_x2(bl, st + XBLO + sw64(boff));
                #pragma unroll
                for (int mf = 0; mf < 2; mf++) {
                    mma16816(acc[mf][nf], ah[mf], bh);
                    mma16816(acc[mf][nf], ah[mf], bl);
                    mma16816(acc[mf][nf], al[mf], bh);
                }
            }
        }
        __syncthreads();
    }

    #pragma unroll
    for (int nf = 0; nf < 8; nf++) {
        int colg = n0 + ncol + 8 * nf + 2 * (lane & 3);
        float2 bv = *(const float2*)(bias + colg);
        #pragma unroll
        for (int mf = 0; mf < 2; mf++) {
            int rowg = m0 + mrow + 16 * mf + (lane >> 2);
            float2 o0 = make_float2(acc[mf][nf][0] + bv.x, acc[mf][nf][1] + bv.y);
            float2 o1 = make_float2(acc[mf][nf][2] + bv.x, acc[mf][nf][3] + bv.y);
            *(float2*)(g_xz + (size_t)rowg * G_ + colg)       = o0;
            *(float2*)(g_xz + (size_t)(rowg + 8) * G_ + colg) = o1;
        }
    }
}

// ---------------------------------------------------------------------------
// Persistent LSTM scan, per-warp pipelined.
// Grid = 128 blocks (1/SM), 128 threads = 4 warps.
// Block owns 32 z-cols (8 u x 4 gates); R slice (hi+lo 128 KB) smem-resident.
// Warp w's A operand = h rows [16w, 16w+16) ONLY -> each warp runs a private
// 4-stage cp.async ring over K chunks; NO intra-step __syncthreads.
// SMEM: R hi 64K | R lo 64K | 4 warps x 4 stages x 4KB (hi 2K + lo 2K) = 192K.
// ---------------------------------------------------------------------------
#define PRHI  0
#define PRLO  65536
#define PHB   131072
#define PSMEM 196608

__global__ __launch_bounds__(128) void lstm_scan(float* __restrict__ out)
{
    extern __shared__ __align__(1024) char sm[];
    uint32_t smb = smem_u32(sm);
    const int tid  = threadIdx.x;
    const int wid  = tid >> 5;
    const int lane = tid & 31;
    const int bid  = blockIdx.x;
    const int u0   = bid * 8;

    const char* rh = (const char*)g_Rt_hi;
    const char* rl = (const char*)g_Rt_lo;

    // ---- Load resident R slice: 16 chunks x (32 cols x 128B), hi+lo ----
    #pragma unroll 4
    for (int i = 0; i < 32; i++) {
        int idx = tid + 128 * i;               // 0..4095 granules
        int kc = idx >> 8;
        int j  = idx & 255;
        int c  = j >> 3, g = j & 7;
        int n  = ((c >> 3) << 10) + u0 + (c & 7);      // gate*1024 + u
        size_t src = (size_t)n * 2048 + kc * 128 + g * 16;
        uint32_t dst = kc * 4096 + sw128(c * 128 + g * 16);
        CP16(smb + PRHI + dst, rh + src);
        CP16(smb + PRLO + dst, rl + src);
    }
    CP_COMMIT(); CP_WAIT0();
    __syncthreads();

    // ---- Per-thread mapping ----
    const int b0   = 16 * wid + (lane >> 2);
    const int uu   = u0 + 2 * (lane & 3);
    const int mi   = lane >> 3;
    const int mr   = lane & 7;
    const int lrow = ((mi & 1) << 3) + mr;          // local A row 0..15
    const int grp  = lane >> 4;                     // 0: R hi, 1: R lo
    const int rrr  = lane & 15;
    const uint32_t wring = smb + PHB + wid * 16384; // this warp's h ring
    float c_reg[4] = {0.f, 0.f, 0.f, 0.f};

    for (int t = 0; t < T_; t++) {
        const char* hh = (const char*)g_hhi[t & 1];
        const char* hl = (const char*)g_hlo[t & 1];

        // xz prefetch (independent of h)
        float2 xzr[2][4];
        #pragma unroll
        for (int half = 0; half < 2; half++) {
            size_t xb = ((size_t)(b0 + 8 * half) * T_ + t) * G_ + uu;
            #pragma unroll
            for (int f = 0; f < 4; f++)
                xzr[half][f] = __ldg((const float2*)(g_xz + xb + f * U_));
        }

        // Warp-private h stage issue: 16 rows x 8 granules, hi+lo (8 CP16/lane)
        auto issue_h = [&](int kc) {
            uint32_t st = wring + (kc & 3) * 4096;
            #pragma unroll
            for (int i = 0; i < 4; i++) {
                int gg = lane + 32 * i;
                int r = gg >> 3, g = gg & 7;
                size_t src = (size_t)(16 * wid + r) * 2048 + (size_t)kc * 128 + g * 16;
                uint32_t so = sw128(r * 128 + g * 16);
                CP16(st + so, hh + src);
                CP16(st + 2048 + so, hl + src);
            }
            CP_COMMIT();
        };

        issue_h(0); issue_h(1); issue_h(2);

        float acc[4][4] = {};   // [gate][frag]

        #pragma unroll 1
        for (int kc = 0; kc < 16; kc++) {
            if (kc <= 13)      { CP_WAIT2(); }
            else if (kc == 14) { CP_WAIT1(); }
            else               { CP_WAIT0(); }
            __syncwarp();

            uint32_t hst = wring + (kc & 3) * 4096;
            uint32_t rbs = smb + (grp ? PRLO : PRHI) + kc * 4096;
            #pragma unroll
            for (int ks = 0; ks < 4; ks++) {
                uint32_t ah[4], al[4];
                uint32_t aoff = sw128(lrow * 128 + ks * 32 + ((mi >> 1) << 4));
                ldsm_x4(ah, hst + aoff);
                ldsm_x4(al, hst + 2048 + aoff);
                #pragma unroll
                for (int f = 0; f < 4; f++) {
                    uint32_t bb[4];   // [0,1]=R hi frags, [2,3]=R lo frags
                    uint32_t boff = sw128((8 * f + (rrr & 7)) * 128 + ks * 32
                                          + (((rrr >> 3) & 1) << 4));
                    ldsm_x4(bb, rbs + boff);
                    mma16816(acc[f], ah, bb);        // Ah * Bh
                    mma16816(acc[f], ah, bb + 2);    // Ah * Bl
                    mma16816(acc[f], al, bb);        // Al * Bh
                }
            }
            if (kc + 3 < 16) issue_h(kc + 3);
        }

        // ---- Gate fusion + state update (c in registers) ----
        __nv_bfloat16* nh_hi = g_hhi[(t + 1) & 1];
        __nv_bfloat16* nh_lo = g_hlo[(t + 1) & 1];
        #pragma unroll
        for (int half = 0; half < 2; half++) {
            int b = b0 + 8 * half;
            float hv[2];
            #pragma unroll
            for (int j = 0; j < 2; j++) {
                int a = 2 * half + j;
                float zi = acc[0][a] + (j ? xzr[half][0].y : xzr[half][0].x);
                float zf = acc[1][a] + (j ? xzr[half][1].y : xzr[half][1].x);
                float zc = acc[2][a] + (j ? xzr[half][2].y : xzr[half][2].x);
                float zo = acc[3][a] + (j ? xzr[half][3].y : xzr[half][3].x);
                float ig = 1.0f / (1.0f + __expf(-zi));
                float fg = 1.0f / (1.0f + __expf(-zf));
                float og = 1.0f / (1.0f + __expf(-zo));
                float cn = fg * c_reg[a] + ig * tanhf(zc);
                c_reg[a] = cn;
                hv[j] = og * tanhf(cn);
            }
            if (t == T_ - 1) {
                *(float2*)(out + b * U_ + uu) = make_float2(hv[0], hv[1]);
            } else {
                __nv_bfloat16 h0 = __float2bfloat16(hv[0]);
                __nv_bfloat16 h1 = __float2bfloat16(hv[1]);
                *(__nv_bfloat162*)(nh_hi + b * U_ + uu) = __halves2bfloat162(h0, h1);
                *(__nv_bfloat162*)(nh_lo + b * U_ + uu) = __halves2bfloat162(
                    __float2bfloat16(hv[0] - __bfloat162float(h0)),
                    __float2bfloat16(hv[1] - __bfloat162float(h1)));
            }
        }

        // ---- Grid barrier: publish our h slice, wait for all 128 blocks ----
        if (t < T_ - 1) {
            __syncthreads();                     // all h writes of this block done
            if (tid == 0) {
                __threadfence();                 // make them visible gpu-wide
                asm volatile("st.release.gpu.global.u32 [%0], %1;"
                             :: "l"(g_flags + t * 128 + bid), "r"(1) : "memory");
            }
            if (tid < 32) {
                const int* fl = g_flags + t * 128 + lane * 4;
                uint4 v;
                while (true) {
                    asm volatile("ld.acquire.gpu.global.v4.u32 {%0,%1,%2,%3}, [%4];"
                                 : "=r"(v.x), "=r"(v.y), "=r"(v.z), "=r"(v.w)
                                 : "l"(fl));
                    if (v.x & v.y & v.z & v.w) break;
                    __nanosleep(30);
                }
            }
            __syncthreads();                     // barrier result visible block-wide
        }
    }
}

// ---------------------------------------------------------------------------
extern "C" void kernel_launch(void* const* d_in, const int* in_sizes, int n_in,
                              void* d_out, int out_size)
{
    const float* x    = (const float*)d_in[0];   // [64, 512, 512]
    const float* W    = (const float*)d_in[1];   // [512, 4096]
    const float* R    = (const float*)d_in[2];   // [1024, 4096]
    const float* bias = (const float*)d_in[3];   // [4096]
    float* out = (float*)d_out;                  // [64, 1024]

    cudaFuncSetAttribute(gemm_xz_mma,
                         cudaFuncAttributeMaxDynamicSharedMemorySize, 2 * XSTG);
    cudaFuncSetAttribute(lstm_scan,
                         cudaFuncAttributeMaxDynamicSharedMemorySize, PSMEM);

    init_state<<<256, 256>>>();
    split_x<<<(B_ * T_ * D_ / 4 + 255) / 256, 256>>>(x);
    transpose_split_sel<<<dim3(G_ / 32, D_ / 32), dim3(32, 8)>>>(W, 0, D_, G_);
    transpose_split_sel<<<dim3(G_ / 32, U_ / 32), dim3(32, 8)>>>(R, 1, U_, G_);
    gemm_xz_mma<<<dim3(G_ / 128, (B_ * T_) / 128), 256, 2 * XSTG>>>(bias);
    lstm_scan<<<128, 128, PSMEM>>>(out);
}

// round 11
// speedup vs baseline: 1.2824x; 1.2824x over previous
#include <cuda_runtime.h>
#include <cuda_bf16.h>
#include <math.h>
#include <stdint.h>

#define B_ 64
#define T_ 512
#define D_ 512
#define U_ 1024
#define G_ 4096   // 4*U

// ---------------------------------------------------------------------------
// Scratch (__device__ globals: allocation-free rule)
// ---------------------------------------------------------------------------
__device__ float         g_xz[(size_t)B_ * T_ * G_];     // fp32 input projections
__device__ __nv_bfloat16 g_xhi[(size_t)B_ * T_ * D_];    // x split
__device__ __nv_bfloat16 g_xlo[(size_t)B_ * T_ * D_];
__device__ __nv_bfloat16 g_Wt_hi[(size_t)G_ * D_];       // W^T split  [4096][512]
__device__ __nv_bfloat16 g_Wt_lo[(size_t)G_ * D_];
__device__ __nv_bfloat16 g_Rt_hi[(size_t)G_ * U_];       // R^T split  [4096][1024]
__device__ __nv_bfloat16 g_Rt_lo[(size_t)G_ * U_];
__device__ __nv_bfloat16 g_hhi[2][B_ * U_];              // h ping-pong, split
__device__ __nv_bfloat16 g_hlo[2][B_ * U_];
__device__ float         g_c[B_ * U_];                   // cell state

// ---------------------------------------------------------------------------
// Helpers
// ---------------------------------------------------------------------------
__device__ __forceinline__ uint32_t smem_u32(const void* p) {
    uint32_t a;
    asm("{ .reg .u64 t; cvta.to.shared.u64 t, %1; cvt.u32.u64 %0, t; }" : "=r"(a) : "l"(p));
    return a;
}
__device__ __forceinline__ uint32_t sw128(uint32_t off) { return off ^ ((off >> 3) & 0x70); }
__device__ __forceinline__ uint32_t sw64 (uint32_t off) { return off ^ ((off >> 3) & 0x30); }

#define CP16(dst, src) \
    asm volatile("cp.async.cg.shared.global [%0], [%1], 16;" :: "r"(dst), "l"(src))
#define CP_COMMIT() asm volatile("cp.async.commit_group;" ::: "memory")
#define CP_WAIT1()  asm volatile("cp.async.wait_group 1;" ::: "memory")
#define CP_WAIT0()  asm volatile("cp.async.wait_group 0;" ::: "memory")

__device__ __forceinline__ void ldsm_x4(uint32_t* r, uint32_t addr) {
    asm volatile("ldmatrix.sync.aligned.m8n8.x4.shared.b16 {%0,%1,%2,%3}, [%4];"
                 : "=r"(r[0]), "=r"(r[1]), "=r"(r[2]), "=r"(r[3]) : "r"(addr));
}
__device__ __forceinline__ void ldsm_x2(uint32_t* r, uint32_t addr) {
    asm volatile("ldmatrix.sync.aligned.m8n8.x2.shared.b16 {%0,%1}, [%2];"
                 : "=r"(r[0]), "=r"(r[1]) : "r"(addr));
}
__device__ __forceinline__ void mma16816(float* c, const uint32_t* a, const uint32_t* b) {
    asm volatile(
        "mma.sync.aligned.m16n8k16.row.col.f32.bf16.bf16.f32 "
        "{%0,%1,%2,%3}, {%4,%5,%6,%7}, {%8,%9}, {%0,%1,%2,%3};"
        : "+f"(c[0]), "+f"(c[1]), "+f"(c[2]), "+f"(c[3])
        : "r"(a[0]), "r"(a[1]), "r"(a[2]), "r"(a[3]), "r"(b[0]), "r"(b[1]));
}

// ---------------------------------------------------------------------------
// Prep kernels
// ---------------------------------------------------------------------------
__global__ void init_state()
{
    int i = blockIdx.x * blockDim.x + threadIdx.x;
    if (i < B_ * U_) {
        __nv_bfloat16 z = __float2bfloat16(0.0f);
        g_hhi[0][i] = z; g_hlo[0][i] = z;
        g_hhi[1][i] = z; g_hlo[1][i] = z;
        g_c[i] = 0.0f;
    }
}

__global__ void split_x(const float* __restrict__ x)
{
    size_t i = (size_t)blockIdx.x * blockDim.x + threadIdx.x;
    size_t n4 = (size_t)B_ * T_ * D_ / 4;
    if (i >= n4) return;
    float4 v = ((const float4*)x)[i];
    float vv[4] = {v.x, v.y, v.z, v.w};
    __nv_bfloat162* ph = (__nv_bfloat162*)g_xhi;
    __nv_bfloat162* pl = (__nv_bfloat162*)g_xlo;
    __nv_bfloat16 h[4], l[4];
    #pragma unroll
    for (int j = 0; j < 4; j++) {
        h[j] = __float2bfloat16(vv[j]);
        l[j] = __float2bfloat16(vv[j] - __bfloat162float(h[j]));
    }
    ph[2*i]     = __halves2bfloat162(h[0], h[1]);
    ph[2*i + 1] = __halves2bfloat162(h[2], h[3]);
    pl[2*i]     = __halves2bfloat162(l[0], l[1]);
    pl[2*i + 1] = __halves2bfloat162(l[2], l[3]);
}

// src [rows][cols] fp32 -> Wt/Rt [cols][rows] bf16 hi/lo (device-resolved dst)
__global__ void transpose_split_sel(const float* __restrict__ src,
                                    int which, int rows, int cols)
{
    __nv_bfloat16* dhi = which ? g_Rt_hi : g_Wt_hi;
    __nv_bfloat16* dlo = which ? g_Rt_lo : g_Wt_lo;
    __shared__ float t[32][33];
    int x = blockIdx.x * 32 + threadIdx.x;
    int y0 = blockIdx.y * 32;
    #pragma unroll
    for (int i = 0; i < 32; i += 8)
        t[threadIdx.y + i][threadIdx.x] = src[(size_t)(y0 + threadIdx.y + i) * cols + x];
    __syncthreads();
    int ox = y0 + threadIdx.x;
    #pragma unroll
    for (int i = 0; i < 32; i += 8) {
        int orow = blockIdx.x * 32 + threadIdx.y + i;
        float v = t[threadIdx.x][threadIdx.y + i];
        __nv_bfloat16 h = __float2bfloat16(v);
        dhi[(size_t)orow * rows + ox] = h;
        dlo[(size_t)orow * rows + ox] = __float2bfloat16(v - __bfloat162float(h));
    }
}

// ---------------------------------------------------------------------------
// xz = x @ W + bias via mma.sync (3-term bf16 split) — unchanged from R7
// ---------------------------------------------------------------------------
#define XAHI 0
#define XALO 8192
#define XBHI 16384
#define XBLO 24576
#define XSTG 32768

__global__ __launch_bounds__(256) void gemm_xz_mma(const float* __restrict__ bias)
{
    extern __shared__ __align__(1024) char sm[];
    uint32_t smb = smem_u32(sm);
    const int tid  = threadIdx.x;
    const int wid  = tid >> 5;
    const int lane = tid & 31;
    const int m0 = blockIdx.y * 128;
    const int n0 = blockIdx.x * 128;

    const char* xh = (const char*)g_xhi;
    const char* xl = (const char*)g_xlo;
    const char* wh = (const char*)g_Wt_hi;
    const char* wl = (const char*)g_Wt_lo;

    float acc[2][8][4] = {};

    auto issue = [&](int kc, int s) {
        uint32_t st = smb + s * XSTG;
        #pragma unroll
        for (int i = 0; i < 2; i++) {
            int idx = tid + 256 * i;
            int r = idx >> 2, g = idx & 3;
            CP16(st + XAHI + sw64(r * 64 + g * 16),
                 xh + (size_t)(m0 + r) * 1024 + kc * 64 + g * 16);
        }
        #pragma unroll
        for (int i = 0; i < 2; i++) {
            int idx = tid + 256 * i;
            int r = idx >> 2, g = idx & 3;
            CP16(st + XALO + sw64(r * 64 + g * 16),
                 xl + (size_t)(m0 + r) * 1024 + kc * 64 + g * 16);
        }
        #pragma unroll
        for (int i = 0; i < 2; i++) {
            int idx = tid + 256 * i;
            int r = idx >> 2, g = idx & 3;
            CP16(st + XBHI + sw64(r * 64 + g * 16),
                 wh + (size_t)(n0 + r) * 1024 + kc * 64 + g * 16);
        }
        #pragma unroll
        for (int i = 0; i < 2; i++) {
            int idx = tid + 256 * i;
            int r = idx >> 2, g = idx & 3;
            CP16(st + XBLO + sw64(r * 64 + g * 16),
                 wl + (size_t)(n0 + r) * 1024 + kc * 64 + g * 16);
        }
    };

    issue(0, 0); CP_COMMIT();

    const int mrow = 32 * (wid >> 1);
    const int ncol = 64 * (wid & 1);
    const int mi  = lane >> 3;
    const int mr  = lane & 7;
    const int rr  = lane & 15;

    for (int kc = 0; kc < 16; kc++) {
        int s = kc & 1;
        if (kc + 1 < 16) { issue(kc + 1, s ^ 1); CP_COMMIT(); CP_WAIT1(); }
        else             { CP_WAIT0(); }
        __syncthreads();

        uint32_t st = smb + s * XSTG;
        #pragma unroll
        for (int ks = 0; ks < 2; ks++) {
            uint32_t ah[2][4], al[2][4];
            #pragma unroll
            for (int mf = 0; mf < 2; mf++) {
                int row = mrow + 16 * mf + ((mi & 1) << 3) + mr;
                uint32_t off = row * 64 + ks * 32 + ((mi >> 1) << 4);
                ldsm_x4(ah[mf], st + XAHI + sw64(off));
                ldsm_x4(al[mf], st + XALO + sw64(off));
            }
            #pragma unroll
            for (int nf = 0; nf < 8; nf++) {
                uint32_t bh[2], bl[2];
                int brow = ncol + 8 * nf + (rr & 7);
                uint32_t boff = brow * 64 + ks * 32 + ((rr >> 3) << 4);
                ldsm_x2(bh, st + XBHI + sw64(boff));
                ldsm_x2(bl, st + XBLO + sw64(boff));
                #pragma unroll
                for (int mf = 0; mf < 2; mf++) {
                    mma16816(acc[mf][nf], ah[mf], bh);
                    mma16816(acc[mf][nf], ah[mf], bl);
                    mma16816(acc[mf][nf], al[mf], bh);
                }
            }
        }
        __syncthreads();
    }

    #pragma unroll
    for (int nf = 0; nf < 8; nf++) {
        int colg = n0 + ncol + 8 * nf + 2 * (lane & 3);
        float2 bv = *(const float2*)(bias + colg);
        #pragma unroll
        for (int mf = 0; mf < 2; mf++) {
            int rowg = m0 + mrow + 16 * mf + (lane >> 2);
            float2 o0 = make_float2(acc[mf][nf][0] + bv.x, acc[mf][nf][1] + bv.y);
            float2 o1 = make_float2(acc[mf][nf][2] + bv.x, acc[mf][nf][3] + bv.y);
            *(float2*)(g_xz + (size_t)rowg * G_ + colg)       = o0;
            *(float2*)(g_xz + (size_t)(rowg + 8) * G_ + colg) = o1;
        }
    }
}

// ---------------------------------------------------------------------------
// One LSTM step, K split across two warp-groups.
// Block = 64 batch x 32 z-cols (8 u x 4 gates). 256 threads = 8 warps:
// group 0 (warps 0-3) -> kc 0..7, group 1 (warps 4-7) -> kc 8..15.
// Each group: private 3-stage cp.async ring, ONE group-local bar.sync per kc.
// Partial accs reduced through smem; group 0 runs the gate epilogue.
// SMEM: 2 groups x 3 stages x 24KB = 144KB + 8.5KB reduction = ~152.5KB.
// ---------------------------------------------------------------------------
#define SAHI 0
#define SALO 8192
#define SBHI 16384
#define SBLO 20480
#define SSTG 24576
#define SRED (6 * SSTG)                 // 147456
#define SSMEM (SRED + 128 * 17 * 4)     // 156160

__global__ __launch_bounds__(256) void lstm_step_mma2(float* __restrict__ out, int t)
{
    extern __shared__ __align__(1024) char sm[];
    uint32_t smb = smem_u32(sm);
    const int tid  = threadIdx.x;
    const int wid  = tid >> 5;       // 0..7
    const int grp  = wid >> 2;       // K-group 0/1
    const int wg   = wid & 3;        // warp within group
    const int lane = tid & 31;
    const int tidg = tid & 127;
    const int u0   = blockIdx.x * 8;

    const char* hh = (const char*)g_hhi[t & 1];
    const char* hl = (const char*)g_hlo[t & 1];
    const char* rh = (const char*)g_Rt_hi;
    const char* rl = (const char*)g_Rt_lo;

    float acc[4][4] = {};   // [gate][frag]

    // Group-cooperative stage load for local chunk kl (global kc = 8*grp+kl)
    auto issue = [&](int kl) {
        int kc = 8 * grp + kl;
        uint32_t st = smb + (3 * grp + (kl % 3)) * SSTG;
        #pragma unroll
        for (int i = 0; i < 4; i++) {      // A hi: 64 rows x 8 granules
            int idx = tidg + 128 * i;
            int r = idx >> 3, g = idx & 7;
            CP16(st + SAHI + sw128(r * 128 + g * 16),
                 hh + (size_t)r * 2048 + (size_t)kc * 128 + g * 16);
        }
        #pragma unroll
        for (int i = 0; i < 4; i++) {      // A lo
            int idx = tidg + 128 * i;
            int r = idx >> 3, g = idx & 7;
            CP16(st + SALO + sw128(r * 128 + g * 16),
                 hl + (size_t)r * 2048 + (size_t)kc * 128 + g * 16);
        }
        #pragma unroll
        for (int i = 0; i < 2; i++) {      // B hi: 32 gathered rows x 8 granules
            int idx = tidg + 128 * i;
            int c = idx >> 3, g = idx & 7;
            int n = ((c >> 3) << 10) + u0 + (c & 7);   // gate*1024 + u
            CP16(st + SBHI + sw128(c * 128 + g * 16),
                 rh + (size_t)n * 2048 + (size_t)kc * 128 + g * 16);
        }
        #pragma unroll
        for (int i = 0; i < 2; i++) {      // B lo
            int idx = tidg + 128 * i;
            int c = idx >> 3, g = idx & 7;
            int n = ((c >> 3) << 10) + u0 + (c & 7);
            CP16(st + SBLO + sw128(c * 128 + g * 16),
                 rl + (size_t)n * 2048 + (size_t)kc * 128 + g * 16);
        }
        CP_COMMIT();
    };

    issue(0);
    issue(1);

    const int mi = lane >> 3;
    const int mr = lane & 7;
    const int rr = lane & 15;

    #pragma unroll 1
    for (int kl = 0; kl < 8; kl++) {
        if (kl < 7) CP_WAIT1(); else CP_WAIT0();
        asm volatile("bar.sync %0, 128;" :: "r"(grp + 1) : "memory");
        if (kl + 2 < 8) issue(kl + 2);

        uint32_t st = smb + (3 * grp + (kl % 3)) * SSTG;
        #pragma unroll
        for (int ks = 0; ks < 4; ks++) {
            uint32_t ah[4], al[4];
            int row = 16 * wg + ((mi & 1) << 3) + mr;
            uint32_t off = row * 128 + ks * 32 + ((mi >> 1) << 4);
            ldsm_x4(ah, st + SAHI + sw128(off));
            ldsm_x4(al, st + SALO + sw128(off));
            #pragma unroll
            for (int f = 0; f < 4; f++) {
                uint32_t bh[2], bl[2];
                int brow = 8 * f + (rr & 7);
                uint32_t boff = brow * 128 + ks * 32 + ((rr >> 3) << 4);
                ldsm_x2(bh, st + SBHI + sw128(boff));
                ldsm_x2(bl, st + SBLO + sw128(boff));
                mma16816(acc[f], ah, bh);
                mma16816(acc[f], ah, bl);
                mma16816(acc[f], al, bh);
            }
        }
    }

    // ---- Cross-group reduction: group 1 partials -> smem -> group 0 ----
    float* red = (float*)(sm + SRED);
    if (grp == 1) {
        #pragma unroll
        for (int f = 0; f < 4; f++)
            #pragma unroll
            for (int a = 0; a < 4; a++)
                red[tidg * 17 + 4 * f + a] = acc[f][a];
    }
    __syncthreads();
    if (grp == 0) {
        #pragma unroll
        for (int f = 0; f < 4; f++)
            #pragma unroll
            for (int a = 0; a < 4; a++)
                acc[f][a] += red[tidg * 17 + 4 * f + a];

        // ---- Gate fusion + state update (R7 epilogue) ----
        const int b0 = 16 * wg + (lane >> 2);
        const int uu = u0 + 2 * (lane & 3);
        __nv_bfloat16* nh_hi = g_hhi[(t + 1) & 1];
        __nv_bfloat16* nh_lo = g_hlo[(t + 1) & 1];

        #pragma unroll
        for (int half = 0; half < 2; half++) {
            int b = b0 + 8 * half;
            size_t xb = ((size_t)b * T_ + t) * G_ + uu;
            float2 xi = *(const float2*)(g_xz + xb);
            float2 xf = *(const float2*)(g_xz + xb + 1 * U_);
            float2 xc = *(const float2*)(g_xz + xb + 2 * U_);
            float2 xo = *(const float2*)(g_xz + xb + 3 * U_);
            float2 cc = *(float2*)(g_c + b * U_ + uu);
            float hv[2];
            #pragma unroll
            for (int j = 0; j < 2; j++) {
                int a = 2 * half + j;
                float zi = acc[0][a] + (j ? xi.y : xi.x);
                float zf = acc[1][a] + (j ? xf.y : xf.x);
                float zc = acc[2][a] + (j ? xc.y : xc.x);
                float zo = acc[3][a] + (j ? xo.y : xo.x);
                float ig = 1.0f / (1.0f + __expf(-zi));
                float fg = 1.0f / (1.0f + __expf(-zf));
                float og = 1.0f / (1.0f + __expf(-zo));
                float cp = j ? cc.y : cc.x;
                float cn = fg * cp + ig * tanhf(zc);
                if (j) cc.y = cn; else cc.x = cn;
                hv[j] = og * tanhf(cn);
            }
            *(float2*)(g_c + b * U_ + uu) = cc;
            if (t == T_ - 1) {
                *(float2*)(out + b * U_ + uu) = make_float2(hv[0], hv[1]);
            } else {
                __nv_bfloat16 h0 = __float2bfloat16(hv[0]);
                __nv_bfloat16 h1 = __float2bfloat16(hv[1]);
                *(__nv_bfloat162*)(nh_hi + b * U_ + uu) = __halves2bfloat162(h0, h1);
                *(__nv_bfloat162*)(nh_lo + b * U_ + uu) = __halves2bfloat162(
                    __float2bfloat16(hv[0] - __bfloat162float(h0)),
                    __float2bfloat16(hv[1] - __bfloat162float(h1)));
            }
        }
    }
}

// ---------------------------------------------------------------------------
extern "C" void kernel_launch(void* const* d_in, const int* in_sizes, int n_in,
                              void* d_out, int out_size)
{
    const float* x    = (const float*)d_in[0];   // [64, 512, 512]
    const float* W    = (const float*)d_in[1];   // [512, 4096]
    const float* R    = (const float*)d_in[2];   // [1024, 4096]
    const float* bias = (const float*)d_in[3];   // [4096]
    float* out = (float*)d_out;                  // [64, 1024]

    cudaFuncSetAttribute(gemm_xz_mma,
                         cudaFuncAttributeMaxDynamicSharedMemorySize, 2 * XSTG);
    cudaFuncSetAttribute(lstm_step_mma2,
                         cudaFuncAttributeMaxDynamicSharedMemorySize, SSMEM);

    init_state<<<256, 256>>>();
    split_x<<<(B_ * T_ * D_ / 4 + 255) / 256, 256>>>(x);
    transpose_split_sel<<<dim3(G_ / 32, D_ / 32), dim3(32, 8)>>>(W, 0, D_, G_);
    transpose_split_sel<<<dim3(G_ / 32, U_ / 32), dim3(32, 8)>>>(R, 1, U_, G_);
    gemm_xz_mma<<<dim3(G_ / 128, (B_ * T_) / 128), 256, 2 * XSTG>>>(bias);
    for (int t = 0; t < T_; t++) {
        lstm_step_mma2<<<128, 256, SSMEM>>>(out, t);
    }
}

// round 12
// speedup vs baseline: 1.5281x; 1.1916x over previous
#include <cuda_runtime.h>
#include <cuda_fp16.h>
#include <math.h>
#include <stdint.h>

#define B_ 64
#define T_ 512
#define D_ 512
#define U_ 1024
#define G_ 4096   // 4*U

// ---------------------------------------------------------------------------
// Scratch (__device__ globals: allocation-free rule)
// ---------------------------------------------------------------------------
__device__ float  g_xz[(size_t)B_ * T_ * G_];     // fp32 input projections
__device__ __half g_xhi[(size_t)B_ * T_ * D_];    // x split (fp16 hi/lo)
__device__ __half g_xlo[(size_t)B_ * T_ * D_];
__device__ __half g_Wt[(size_t)G_ * D_];          // W^T single fp16  [4096][512]
__device__ __half g_Rt[(size_t)G_ * U_];          // R^T single fp16  [4096][1024]
__device__ __half g_hhi[2][B_ * U_];              // h ping-pong, fp16 hi/lo
__device__ __half g_hlo[2][B_ * U_];
__device__ float  g_c[B_ * U_];                   // cell state

// ---------------------------------------------------------------------------
// Helpers
// ---------------------------------------------------------------------------
__device__ __forceinline__ uint32_t smem_u32(const void* p) {
    uint32_t a;
    asm("{ .reg .u64 t; cvta.to.shared.u64 t, %1; cvt.u32.u64 %0, t; }" : "=r"(a) : "l"(p));
    return a;
}
__device__ __forceinline__ uint32_t sw128(uint32_t off) { return off ^ ((off >> 3) & 0x70); }
__device__ __forceinline__ uint32_t sw64 (uint32_t off) { return off ^ ((off >> 3) & 0x30); }

#define CP16(dst, src) \
    asm volatile("cp.async.cg.shared.global [%0], [%1], 16;" :: "r"(dst), "l"(src))
#define CP_COMMIT() asm volatile("cp.async.commit_group;" ::: "memory")
#define CP_WAIT1()  asm volatile("cp.async.wait_group 1;" ::: "memory")
#define CP_WAIT0()  asm volatile("cp.async.wait_group 0;" ::: "memory")

__device__ __forceinline__ void ldsm_x4(uint32_t* r, uint32_t addr) {
    asm volatile("ldmatrix.sync.aligned.m8n8.x4.shared.b16 {%0,%1,%2,%3}, [%4];"
                 : "=r"(r[0]), "=r"(r[1]), "=r"(r[2]), "=r"(r[3]) : "r"(addr));
}
__device__ __forceinline__ void ldsm_x2(uint32_t* r, uint32_t addr) {
    asm volatile("ldmatrix.sync.aligned.m8n8.x2.shared.b16 {%0,%1}, [%2];"
                 : "=r"(r[0]), "=r"(r[1]) : "r"(addr));
}
__device__ __forceinline__ void mma16816(float* c, const uint32_t* a, const uint32_t* b) {
    asm volatile(
        "mma.sync.aligned.m16n8k16.row.col.f32.f16.f16.f32 "
        "{%0,%1,%2,%3}, {%4,%5,%6,%7}, {%8,%9}, {%0,%1,%2,%3};"
        : "+f"(c[0]), "+f"(c[1]), "+f"(c[2]), "+f"(c[3])
        : "r"(a[0]), "r"(a[1]), "r"(a[2]), "r"(a[3]), "r"(b[0]), "r"(b[1]));
}

// ---------------------------------------------------------------------------
// Prep kernels
// ---------------------------------------------------------------------------
__global__ void init_state()
{
    int i = blockIdx.x * blockDim.x + threadIdx.x;
    if (i < B_ * U_) {
        __half z = __float2half(0.0f);
        g_hhi[0][i] = z; g_hlo[0][i] = z;
        g_hhi[1][i] = z; g_hlo[1][i] = z;
        g_c[i] = 0.0f;
    }
}

__global__ void split_x(const float* __restrict__ x)
{
    size_t i = (size_t)blockIdx.x * blockDim.x + threadIdx.x;
    size_t n4 = (size_t)B_ * T_ * D_ / 4;
    if (i >= n4) return;
    float4 v = ((const float4*)x)[i];
    float vv[4] = {v.x, v.y, v.z, v.w};
    __half2* ph = (__half2*)g_xhi;
    __half2* pl = (__half2*)g_xlo;
    __half h[4], l[4];
    #pragma unroll
    for (int j = 0; j < 4; j++) {
        h[j] = __float2half_rn(vv[j]);
        l[j] = __float2half_rn(vv[j] - __half2float(h[j]));
    }
    ph[2*i]     = __halves2half2(h[0], h[1]);
    ph[2*i + 1] = __halves2half2(h[2], h[3]);
    pl[2*i]     = __halves2half2(l[0], l[1]);
    pl[2*i + 1] = __halves2half2(l[2], l[3]);
}

// src [rows][cols] fp32 -> Wt/Rt [cols][rows] single fp16 (device-resolved dst)
__global__ void transpose_h16_sel(const float* __restrict__ src,
                                  int which, int rows, int cols)
{
    __half* dst = which ? g_Rt : g_Wt;
    __shared__ float t[32][33];
    int x = blockIdx.x * 32 + threadIdx.x;
    int y0 = blockIdx.y * 32;
    #pragma unroll
    for (int i = 0; i < 32; i += 8)
        t[threadIdx.y + i][threadIdx.x] = src[(size_t)(y0 + threadIdx.y + i) * cols + x];
    __syncthreads();
    int ox = y0 + threadIdx.x;
    #pragma unroll
    for (int i = 0; i < 32; i += 8) {
        int orow = blockIdx.x * 32 + threadIdx.y + i;
        dst[(size_t)orow * rows + ox] = __float2half_rn(t[threadIdx.x][threadIdx.y + i]);
    }
}

// ---------------------------------------------------------------------------
// xz = x @ W + bias via mma.sync, fp16 2-term: Ah*B + Al*B  (x split, W fp16)
// Block tile 128m x 128n, K=512 in 16 chunks of 32 (64B rows, sw64 swizzle).
// 256 threads = 8 warps (4m x 2n); warp tile 32 x 64 (2 mfrag x 8 nfrag).
// ---------------------------------------------------------------------------
#define XAHI 0
#define XALO 8192
#define XBHI 16384
#define XSTG 24576   // one stage (24 KB); 2 stages = 48 KB dynamic smem

__global__ __launch_bounds__(256) void gemm_xz_mma(const float* __restrict__ bias)
{
    extern __shared__ __align__(1024) char sm[];
    uint32_t smb = smem_u32(sm);
    const int tid  = threadIdx.x;
    const int wid  = tid >> 5;
    const int lane = tid & 31;
    const int m0 = blockIdx.y * 128;
    const int n0 = blockIdx.x * 128;

    const char* xh = (const char*)g_xhi;
    const char* xl = (const char*)g_xlo;
    const char* wh = (const char*)g_Wt;

    float acc[2][8][4] = {};

    auto issue = [&](int kc, int s) {
        uint32_t st = smb + s * XSTG;
        #pragma unroll
        for (int i = 0; i < 2; i++) {      // A hi: 128 rows x 4 granules
            int idx = tid + 256 * i;
            int r = idx >> 2, g = idx & 3;
            CP16(st + XAHI + sw64(r * 64 + g * 16),
                 xh + (size_t)(m0 + r) * 1024 + kc * 64 + g * 16);
        }
        #pragma unroll
        for (int i = 0; i < 2; i++) {      // A lo
            int idx = tid + 256 * i;
            int r = idx >> 2, g = idx & 3;
            CP16(st + XALO + sw64(r * 64 + g * 16),
                 xl + (size_t)(m0 + r) * 1024 + kc * 64 + g * 16);
        }
        #pragma unroll
        for (int i = 0; i < 2; i++) {      // B: 128 rows x 4 granules
            int idx = tid + 256 * i;
            int r = idx >> 2, g = idx & 3;
            CP16(st + XBHI + sw64(r * 64 + g * 16),
                 wh + (size_t)(n0 + r) * 1024 + kc * 64 + g * 16);
        }
    };

    issue(0, 0); CP_COMMIT();

    const int mrow = 32 * (wid >> 1);
    const int ncol = 64 * (wid & 1);
    const int mi  = lane >> 3;
    const int mr  = lane & 7;
    const int rr  = lane & 15;

    for (int kc = 0; kc < 16; kc++) {
        int s = kc & 1;
        if (kc + 1 < 16) { issue(kc + 1, s ^ 1); CP_COMMIT(); CP_WAIT1(); }
        else             { CP_WAIT0(); }
        __syncthreads();

        uint32_t st = smb + s * XSTG;
        #pragma unroll
        for (int ks = 0; ks < 2; ks++) {
            uint32_t ah[2][4], al[2][4];
            #pragma unroll
            for (int mf = 0; mf < 2; mf++) {
                int row = mrow + 16 * mf + ((mi & 1) << 3) + mr;
                uint32_t off = row * 64 + ks * 32 + ((mi >> 1) << 4);
                ldsm_x4(ah[mf], st + XAHI + sw64(off));
                ldsm_x4(al[mf], st + XALO + sw64(off));
            }
            #pragma unroll
            for (int nf = 0; nf < 8; nf++) {
                uint32_t bh[2];
                int brow = ncol + 8 * nf + (rr & 7);
                uint32_t boff = brow * 64 + ks * 32 + ((rr >> 3) << 4);
                ldsm_x2(bh, st + XBHI + sw64(boff));
                #pragma unroll
                for (int mf = 0; mf < 2; mf++) {
                    mma16816(acc[mf][nf], ah[mf], bh);
                    mma16816(acc[mf][nf], al[mf], bh);
                }
            }
        }
        __syncthreads();
    }

    #pragma unroll
    for (int nf = 0; nf < 8; nf++) {
        int colg = n0 + ncol + 8 * nf + 2 * (lane & 3);
        float2 bv = *(const float2*)(bias + colg);
        #pragma unroll
        for (int mf = 0; mf < 2; mf++) {
            int rowg = m0 + mrow + 16 * mf + (lane >> 2);
            float2 o0 = make_float2(acc[mf][nf][0] + bv.x, acc[mf][nf][1] + bv.y);
            float2 o1 = make_float2(acc[mf][nf][2] + bv.x, acc[mf][nf][3] + bv.y);
            *(float2*)(g_xz + (size_t)rowg * G_ + colg)       = o0;
            *(float2*)(g_xz + (size_t)(rowg + 8) * G_ + colg) = o1;
        }
    }
}

// ---------------------------------------------------------------------------
// One LSTM step via mma.sync, fp16 2-term (h split hi/lo, R single fp16).
// Block = 64 batch x 32 z-cols (8 u x 4 gates; nfrag f == gate f).
// 128 threads = 4 warps; warp tile 16m x 32n. K=1024 in 16 chunks of 64
// (128B rows, sw128). Gate fusion fully in-register.
// ---------------------------------------------------------------------------
#define SAHI 0
#define SALO 8192
#define SBHI 16384
#define SSTG 20480   // one stage (20 KB); 2 stages = 40 KB static smem

__global__ __launch_bounds__(128) void lstm_step_mma(float* __restrict__ out, int t)
{
    __shared__ __align__(1024) char sm[2 * SSTG];
    uint32_t smb = smem_u32(sm);
    const int tid  = threadIdx.x;
    const int wid  = tid >> 5;
    const int lane = tid & 31;
    const int u0 = blockIdx.x * 8;

    const char* hh = (const char*)g_hhi[t & 1];
    const char* hl = (const char*)g_hlo[t & 1];
    const char* rh = (const char*)g_Rt;

    float acc[4][4] = {};   // [gate][frag]

    auto issue = [&](int kc, int s) {
        uint32_t st = smb + s * SSTG;
        #pragma unroll
        for (int i = 0; i < 4; i++) {      // A hi: 64 rows x 8 granules
            int idx = tid + 128 * i;
            int r = idx >> 3, g = idx & 7;
            CP16(st + SAHI + sw128(r * 128 + g * 16),
                 hh + (size_t)r * 2048 + kc * 128 + g * 16);
        }
        #pragma unroll
        for (int i = 0; i < 4; i++) {      // A lo
            int idx = tid + 128 * i;
            int r = idx >> 3, g = idx & 7;
            CP16(st + SALO + sw128(r * 128 + g * 16),
                 hl + (size_t)r * 2048 + kc * 128 + g * 16);
        }
        #pragma unroll
        for (int i = 0; i < 2; i++) {      // B: 32 rows (gathered) x 8 granules
            int idx = tid + 128 * i;
            int c = idx >> 3, g = idx & 7;
            int n = ((c >> 3) << 10) + u0 + (c & 7);   // gate*1024 + u
            CP16(st + SBHI + sw128(c * 128 + g * 16),
                 rh + (size_t)n * 2048 + kc * 128 + g * 16);
        }
    };

    issue(0, 0); CP_COMMIT();

    const int mi = lane >> 3;
    const int mr = lane & 7;
    const int rr = lane & 15;

    for (int kc = 0; kc < 16; kc++) {
        int s = kc & 1;
        if (kc + 1 < 16) { issue(kc + 1, s ^ 1); CP_COMMIT(); CP_WAIT1(); }
        else             { CP_WAIT0(); }
        __syncthreads();

        uint32_t st = smb + s * SSTG;
        #pragma unroll
        for (int ks = 0; ks < 4; ks++) {
            uint32_t ah[4], al[4];
            int row = 16 * wid + ((mi & 1) << 3) + mr;
            uint32_t off = row * 128 + ks * 32 + ((mi >> 1) << 4);
            ldsm_x4(ah, st + SAHI + sw128(off));
            ldsm_x4(al, st + SALO + sw128(off));
            #pragma unroll
            for (int f = 0; f < 4; f++) {
                uint32_t bh[2];
                int brow = 8 * f + (rr & 7);
                uint32_t boff = brow * 128 + ks * 32 + ((rr >> 3) << 4);
                ldsm_x2(bh, st + SBHI + sw128(boff));
                mma16816(acc[f], ah, bh);
                mma16816(acc[f], al, bh);
            }
        }
        __syncthreads();
    }

    // Epilogue: fully in-register gate fusion + state update.
    const int b0 = 16 * wid + (lane >> 2);
    const int uu = u0 + 2 * (lane & 3);
    __half* nh_hi = g_hhi[(t + 1) & 1];
    __half* nh_lo = g_hlo[(t + 1) & 1];

    #pragma unroll
    for (int half = 0; half < 2; half++) {
        int b = b0 + 8 * half;
        size_t xb = ((size_t)b * T_ + t) * G_ + uu;
        float2 xi = *(const float2*)(g_xz + xb);
        float2 xf = *(const float2*)(g_xz + xb + 1 * U_);
        float2 xc = *(const float2*)(g_xz + xb + 2 * U_);
        float2 xo = *(const float2*)(g_xz + xb + 3 * U_);
        float2 cc = *(float2*)(g_c + b * U_ + uu);
        float hv[2];
        #pragma unroll
        for (int j = 0; j < 2; j++) {
            int a = 2 * half + j;
            float zi = acc[0][a] + (j ? xi.y : xi.x);
            float zf = acc[1][a] + (j ? xf.y : xf.x);
            float zc = acc[2][a] + (j ? xc.y : xc.x);
            float zo = acc[3][a] + (j ? xo.y : xo.x);
            float ig = 1.0f / (1.0f + __expf(-zi));
            float fg = 1.0f / (1.0f + __expf(-zf));
            float og = 1.0f / (1.0f + __expf(-zo));
            float cp = j ? cc.y : cc.x;
            float cn = fg * cp + ig * tanhf(zc);
            if (j) cc.y = cn; else cc.x = cn;
            hv[j] = og * tanhf(cn);
        }
        *(float2*)(g_c + b * U_ + uu) = cc;
        if (t == T_ - 1) {
            *(float2*)(out + b * U_ + uu) = make_float2(hv[0], hv[1]);
        } else {
            __half h0 = __float2half_rn(hv[0]);
            __half h1 = __float2half_rn(hv[1]);
            *(__half2*)(nh_hi + b * U_ + uu) = __halves2half2(h0, h1);
            *(__half2*)(nh_lo + b * U_ + uu) = __halves2half2(
                __float2half_rn(hv[0] - __half2float(h0)),
                __float2half_rn(hv[1] - __half2float(h1)));
        }
    }
}

// ---------------------------------------------------------------------------
extern "C" void kernel_launch(void* const* d_in, const int* in_sizes, int n_in,
                              void* d_out, int out_size)
{
    const float* x    = (const float*)d_in[0];   // [64, 512, 512]
    const float* W    = (const float*)d_in[1];   // [512, 4096]
    const float* R    = (const float*)d_in[2];   // [1024, 4096]
    const float* bias = (const float*)d_in[3];   // [4096]
    float* out = (float*)d_out;                  // [64, 1024]

    cudaFuncSetAttribute(gemm_xz_mma,
                         cudaFuncAttributeMaxDynamicSharedMemorySize, 2 * XSTG);

    init_state<<<256, 256>>>();
    split_x<<<(B_ * T_ * D_ / 4 + 255) / 256, 256>>>(x);
    transpose_h16_sel<<<dim3(G_ / 32, D_ / 32), dim3(32, 8)>>>(W, 0, D_, G_);
    transpose_h16_sel<<<dim3(G_ / 32, U_ / 32), dim3(32, 8)>>>(R, 1, U_, G_);
    gemm_xz_mma<<<dim3(G_ / 128, (B_ * T_) / 128), 256, 2 * XSTG>>>(bias);
    for (int t = 0; t < T_; t++) {
        lstm_step_mma<<<128, 128>>>(out, t);
    }
}

// round 15
// speedup vs baseline: 1.6665x; 1.0906x over previous
#include <cuda_runtime.h>
#include <cuda_fp16.h>
#include <math.h>
#include <stdint.h>

#define B_ 64
#define T_ 512
#define D_ 512
#define U_ 1024
#define G_ 4096   // 4*U

// ---------------------------------------------------------------------------
// Scratch (__device__ globals: allocation-free rule)
// ---------------------------------------------------------------------------
__device__ float  g_xz[(size_t)B_ * T_ * G_];     // fp32 input projections
__device__ __half g_xhi[(size_t)B_ * T_ * D_];    // x split (fp16 hi/lo)
__device__ __half g_xlo[(size_t)B_ * T_ * D_];
__device__ __half g_Wt[(size_t)G_ * D_];          // W^T single fp16  [4096][512]
__device__ __half g_Rt[(size_t)G_ * U_];          // R^T single fp16  [4096][1024]
__device__ __half g_h[2][B_ * U_];                // h ping-pong, single fp16
__device__ float  g_c[B_ * U_];                   // cell state

// ---------------------------------------------------------------------------
// Helpers
// ---------------------------------------------------------------------------
__device__ __forceinline__ uint32_t smem_u32(const void* p) {
    uint32_t a;
    asm("{ .reg .u64 t; cvta.to.shared.u64 t, %1; cvt.u32.u64 %0, t; }" : "=r"(a) : "l"(p));
    return a;
}
__device__ __forceinline__ uint32_t sw128(uint32_t off) { return off ^ ((off >> 3) & 0x70); }
__device__ __forceinline__ uint32_t sw64 (uint32_t off) { return off ^ ((off >> 3) & 0x30); }

#define CP16(dst, src) \
    asm volatile("cp.async.cg.shared.global [%0], [%1], 16;" :: "r"(dst), "l"(src))
#define CP_COMMIT() asm volatile("cp.async.commit_group;" ::: "memory")
#define CP_WAIT1()  asm volatile("cp.async.wait_group 1;" ::: "memory")
#define CP_WAIT0()  asm volatile("cp.async.wait_group 0;" ::: "memory")

__device__ __forceinline__ void ldsm_x4(uint32_t* r, uint32_t addr) {
    asm volatile("ldmatrix.sync.aligned.m8n8.x4.shared.b16 {%0,%1,%2,%3}, [%4];"
                 : "=r"(r[0]), "=r"(r[1]), "=r"(r[2]), "=r"(r[3]) : "r"(addr));
}
__device__ __forceinline__ void ldsm_x2(uint32_t* r, uint32_t addr) {
    asm volatile("ldmatrix.sync.aligned.m8n8.x2.shared.b16 {%0,%1}, [%2];"
                 : "=r"(r[0]), "=r"(r[1]) : "r"(addr));
}
__device__ __forceinline__ void mma16816(float* c, const uint32_t* a, const uint32_t* b) {
    asm volatile(
        "mma.sync.aligned.m16n8k16.row.col.f32.f16.f16.f32 "
        "{%0,%1,%2,%3}, {%4,%5,%6,%7}, {%8,%9}, {%0,%1,%2,%3};"
        : "+f"(c[0]), "+f"(c[1]), "+f"(c[2]), "+f"(c[3])
        : "r"(a[0]), "r"(a[1]), "r"(a[2]), "r"(a[3]), "r"(b[0]), "r"(b[1]));
}

// ---------------------------------------------------------------------------
// Prep kernels
// ---------------------------------------------------------------------------
__global__ void init_state()
{
    int i = blockIdx.x * blockDim.x + threadIdx.x;
    if (i < B_ * U_) {
        __half z = __float2half(0.0f);
        g_h[0][i] = z;
        g_h[1][i] = z;
        g_c[i] = 0.0f;
    }
}

__global__ void split_x(const float* __restrict__ x)
{
    size_t i = (size_t)blockIdx.x * blockDim.x + threadIdx.x;
    size_t n4 = (size_t)B_ * T_ * D_ / 4;
    if (i >= n4) return;
    float4 v = ((const float4*)x)[i];
    float vv[4] = {v.x, v.y, v.z, v.w};
    __half2* ph = (__half2*)g_xhi;
    __half2* pl = (__half2*)g_xlo;
    __half h[4], l[4];
    #pragma unroll
    for (int j = 0; j < 4; j++) {
        h[j] = __float2half_rn(vv[j]);
        l[j] = __float2half_rn(vv[j] - __half2float(h[j]));
    }
    ph[2*i]     = __halves2half2(h[0], h[1]);
    ph[2*i + 1] = __halves2half2(h[2], h[3]);
    pl[2*i]     = __halves2half2(l[0], l[1]);
    pl[2*i + 1] = __halves2half2(l[2], l[3]);
}

// src [rows][cols] fp32 -> Wt/Rt [cols][rows] single fp16 (device-resolved dst)
__global__ void transpose_h16_sel(const float* __restrict__ src,
                                  int which, int rows, int cols)
{
    __half* dst = which ? g_Rt : g_Wt;
    __shared__ float t[32][33];
    int x = blockIdx.x * 32 + threadIdx.x;
    int y0 = blockIdx.y * 32;
    #pragma unroll
    for (int i = 0; i < 32; i += 8)
        t[threadIdx.y + i][threadIdx.x] = src[(size_t)(y0 + threadIdx.y + i) * cols + x];
    __syncthreads();
    int ox = y0 + threadIdx.x;
    #pragma unroll
    for (int i = 0; i < 32; i += 8) {
        int orow = blockIdx.x * 32 + threadIdx.y + i;
        dst[(size_t)orow * rows + ox] = __float2half_rn(t[threadIdx.x][threadIdx.y + i]);
    }
}

// ---------------------------------------------------------------------------
// xz = x @ W + bias via mma.sync, fp16 2-term: Ah*B + Al*B  (x split, W fp16)
// Block tile 128m x 128n, K=512 in 16 chunks of 32 (64B rows, sw64 swizzle).
// 256 threads = 8 warps (4m x 2n); warp tile 32 x 64 (2 mfrag x 8 nfrag).
// ---------------------------------------------------------------------------
#define XAHI 0
#define XALO 8192
#define XBHI 16384
#define XSTG 24576   // one stage (24 KB); 2 stages = 48 KB dynamic smem

__global__ __launch_bounds__(256) void gemm_xz_mma(const float* __restrict__ bias)
{
    extern __shared__ __align__(1024) char sm[];
    uint32_t smb = smem_u32(sm);
    const int tid  = threadIdx.x;
    const int wid  = tid >> 5;
    const int lane = tid & 31;
    const int m0 = blockIdx.y * 128;
    const int n0 = blockIdx.x * 128;

    const char* xh = (const char*)g_xhi;
    const char* xl = (const char*)g_xlo;
    const char* wh = (const char*)g_Wt;

    float acc[2][8][4] = {};

    auto issue = [&](int kc, int s) {
        uint32_t st = smb + s * XSTG;
        #pragma unroll
        for (int i = 0; i < 2; i++) {      // A hi: 128 rows x 4 granules
            int idx = tid + 256 * i;
            int r = idx >> 2, g = idx & 3;
            CP16(st + XAHI + sw64(r * 64 + g * 16),
                 xh + (size_t)(m0 + r) * 1024 + kc * 64 + g * 16);
        }
        #pragma unroll
        for (int i = 0; i < 2; i++) {      // A lo
            int idx = tid + 256 * i;
            int r = idx >> 2, g = idx & 3;
            CP16(st + XALO + sw64(r * 64 + g * 16),
                 xl + (size_t)(m0 + r) * 1024 + kc * 64 + g * 16);
        }
        #pragma unroll
        for (int i = 0; i < 2; i++) {      // B: 128 rows x 4 granules
            int idx = tid + 256 * i;
            int r = idx >> 2, g = idx & 3;
            CP16(st + XBHI + sw64(r * 64 + g * 16),
                 wh + (size_t)(n0 + r) * 1024 + kc * 64 + g * 16);
        }
    };

    issue(0, 0); CP_COMMIT();

    const int mrow = 32 * (wid >> 1);
    const int ncol = 64 * (wid & 1);
    const int mi  = lane >> 3;
    const int mr  = lane & 7;
    const int rr  = lane & 15;

    for (int kc = 0; kc < 16; kc++) {
        int s = kc & 1;
        if (kc + 1 < 16) { issue(kc + 1, s ^ 1); CP_COMMIT(); CP_WAIT1(); }
        else             { CP_WAIT0(); }
        __syncthreads();

        uint32_t st = smb + s * XSTG;
        #pragma unroll
        for (int ks = 0; ks < 2; ks++) {
            uint32_t ah[2][4], al[2][4];
            #pragma unroll
            for (int mf = 0; mf < 2; mf++) {
                int row = mrow + 16 * mf + ((mi & 1) << 3) + mr;
                uint32_t off = row * 64 + ks * 32 + ((mi >> 1) << 4);
                ldsm_x4(ah[mf], st + XAHI + sw64(off));
                ldsm_x4(al[mf], st + XALO + sw64(off));
            }
            #pragma unroll
            for (int nf = 0; nf < 8; nf++) {
                uint32_t bh[2];
                int brow = ncol + 8 * nf + (rr & 7);
                uint32_t boff = brow * 64 + ks * 32 + ((rr >> 3) << 4);
                ldsm_x2(bh, st + XBHI + sw64(boff));
                #pragma unroll
                for (int mf = 0; mf < 2; mf++) {
                    mma16816(acc[mf][nf], ah[mf], bh);
                    mma16816(acc[mf][nf], al[mf], bh);
                }
            }
        }
        __syncthreads();
    }

    #pragma unroll
    for (int nf = 0; nf < 8; nf++) {
        int colg = n0 + ncol + 8 * nf + 2 * (lane & 3);
        float2 bv = *(const float2*)(bias + colg);
        #pragma unroll
        for (int mf = 0; mf < 2; mf++) {
            int rowg = m0 + mrow + 16 * mf + (lane >> 2);
            float2 o0 = make_float2(acc[mf][nf][0] + bv.x, acc[mf][nf][1] + bv.y);
            float2 o1 = make_float2(acc[mf][nf][2] + bv.x, acc[mf][nf][3] + bv.y);
            *(float2*)(g_xz + (size_t)rowg * G_ + colg)       = o0;
            *(float2*)(g_xz + (size_t)(rowg + 8) * G_ + colg) = o1;
        }
    }
}

// ---------------------------------------------------------------------------
// One LSTM step via mma.sync, fp16 1-term (h single fp16, R single fp16).
// Block = 64 batch x 32 z-cols (8 u x 4 gates; nfrag f == gate f).
// 128 threads = 4 warps; warp tile 16m x 32n; 256 mma/warp/step.
// K=1024 in 16 chunks of 64 (128B rows, sw128), 3-stage ring, 1 sync/chunk.
// ---------------------------------------------------------------------------
#define SA   0
#define SB   8192
#define SSTG 12288   // one stage (12 KB); 3 stages = 36 KB static smem

__global__ __launch_bounds__(128) void lstm_step_mma(float* __restrict__ out, int t)
{
    __shared__ __align__(1024) char sm[3 * SSTG];
    uint32_t smb = smem_u32(sm);
    const int tid  = threadIdx.x;
    const int wid  = tid >> 5;
    const int lane = tid & 31;
    const int u0 = blockIdx.x * 8;

    const char* hp = (const char*)g_h[t & 1];
    const char* rp = (const char*)g_Rt;

    float acc[4][4] = {};   // [gate][frag]

    auto issue = [&](int kc) {
        uint32_t st = smb + (kc % 3) * SSTG;
        #pragma unroll
        for (int i = 0; i < 4; i++) {      // A (h): 64 rows x 8 granules
            int idx = tid + 128 * i;
            int r = idx >> 3, g = idx & 7;
            CP16(st + SA + sw128(r * 128 + g * 16),
                 hp + (size_t)r * 2048 + kc * 128 + g * 16);
        }
        #pragma unroll
        for (int i = 0; i < 2; i++) {      // B (R gathered): 32 rows x 8 granules
            int idx = tid + 128 * i;
            int c = idx >> 3, g = idx & 7;
            int n = ((c >> 3) << 10) + u0 + (c & 7);   // gate*1024 + u
            CP16(st + SB + sw128(c * 128 + g * 16),
                 rp + (size_t)n * 2048 + kc * 128 + g * 16);
        }
        CP_COMMIT();
    };

    issue(0);
    issue(1);

    const int mi = lane >> 3;
    const int mr = lane & 7;
    const int rr = lane & 15;

    #pragma unroll 1
    for (int kc = 0; kc < 16; kc++) {
        if (kc < 15) CP_WAIT1(); else CP_WAIT0();
        __syncthreads();                    // chunk kc ready; all warps past kc-1

        uint32_t st = smb + (kc % 3) * SSTG;
        #pragma unroll
        for (int ks = 0; ks < 4; ks++) {
            uint32_t ah[4];
            int row = 16 * wid + ((mi & 1) << 3) + mr;
            uint32_t off = row * 128 + ks * 32 + ((mi >> 1) << 4);
            ldsm_x4(ah, st + SA + sw128(off));
            #pragma unroll
            for (int f = 0; f < 4; f++) {
                uint32_t bh[2];
                int brow = 8 * f + (rr & 7);
                uint32_t boff = brow * 128 + ks * 32 + ((rr >> 3) << 4);
                ldsm_x2(bh, st + SB + sw128(boff));
                mma16816(acc[f], ah, bh);
            }
        }
        if (kc + 2 < 16) issue(kc + 2);     // safe: targets stage read at kc-1
    }

    // Epilogue: fully in-register gate fusion + state update.
    const int b0 = 16 * wid + (lane >> 2);
    const int uu = u0 + 2 * (lane & 3);
    __half* nh = g_h[(t + 1) & 1];

    #pragma unroll
    for (int half = 0; half < 2; half++) {
        int b = b0 + 8 * half;
        size_t xb = ((size_t)b * T_ + t) * G_ + uu;
        float2 xi = *(const float2*)(g_xz + xb);
        float2 xf = *(const float2*)(g_xz + xb + 1 * U_);
        float2 xc = *(const float2*)(g_xz + xb + 2 * U_);
        float2 xo = *(const float2*)(g_xz + xb + 3 * U_);
        float2 cc = *(float2*)(g_c + b * U_ + uu);
        float hv[2];
        #pragma unroll
        for (int j = 0; j < 2; j++) {
            int a = 2 * half + j;
            float zi = acc[0][a] + (j ? xi.y : xi.x);
            float zf = acc[1][a] + (j ? xf.y : xf.x);
            float zc = acc[2][a] + (j ? xc.y : xc.x);
            float zo = acc[3][a] + (j ? xo.y : xo.x);
            float ig = 1.0f / (1.0f + __expf(-zi));
            float fg = 1.0f / (1.0f + __expf(-zf));
            float og = 1.0f / (1.0f + __expf(-zo));
            float cp = j ? cc.y : cc.x;
            float cn = fg * cp + ig * tanhf(zc);
            if (j) cc.y = cn; else cc.x = cn;
            hv[j] = og * tanhf(cn);
        }
        *(float2*)(g_c + b * U_ + uu) = cc;
        if (t == T_ - 1) {
            *(float2*)(out + b * U_ + uu) = make_float2(hv[0], hv[1]);
        } else {
            *(__half2*)(nh + b * U_ + uu) =
                __halves2half2(__float2half_rn(hv[0]), __float2half_rn(hv[1]));
        }
    }
}

// ---------------------------------------------------------------------------
extern "C" void kernel_launch(void* const* d_in, const int* in_sizes, int n_in,
                              void* d_out, int out_size)
{
    const float* x    = (const float*)d_in[0];   // [64, 512, 512]
    const float* W    = (const float*)d_in[1];   // [512, 4096]
    const float* R    = (const float*)d_in[2];   // [1024, 4096]
    const float* bias = (const float*)d_in[3];   // [4096]
    float* out = (float*)d_out;                  // [64, 1024]

    cudaFuncSetAttribute(gemm_xz_mma,
                         cudaFuncAttributeMaxDynamicSharedMemorySize, 2 * XSTG);

    init_state<<<256, 256>>>();
    split_x<<<(B_ * T_ * D_ / 4 + 255) / 256, 256>>>(x);
    transpose_h16_sel<<<dim3(G_ / 32, D_ / 32), dim3(32, 8)>>>(W, 0, D_, G_);
    transpose_h16_sel<<<dim3(G_ / 32, U_ / 32), dim3(32, 8)>>>(R, 1, U_, G_);
    gemm_xz_mma<<<dim3(G_ / 128, (B_ * T_) / 128), 256, 2 * XSTG>>>(bias);
    for (int t = 0; t < T_; t++) {
        lstm_step_mma<<<128, 128>>>(out, t);
    }
}

// round 17
// speedup vs baseline: 1.7589x; 1.0555x over previous
#include <cuda_runtime.h>
#include <cuda_fp16.h>
#include <math.h>
#include <stdint.h>

#define B_ 64
#define T_ 512
#define D_ 512
#define U_ 1024
#define G_ 4096   // 4*U

// ---------------------------------------------------------------------------
// Scratch (__device__ globals: allocation-free rule)
// ---------------------------------------------------------------------------
__device__ float  g_xz[(size_t)B_ * T_ * G_];     // fp32 input projections
__device__ __half g_xhi[(size_t)B_ * T_ * D_];    // x split (fp16 hi/lo)
__device__ __half g_xlo[(size_t)B_ * T_ * D_];
__device__ __half g_Wt[(size_t)G_ * D_];          // W^T single fp16  [4096][512]
__device__ __half g_Rt[(size_t)G_ * U_];          // R^T single fp16  [4096][1024]
__device__ __half g_h[2][B_ * U_];                // h ping-pong, single fp16
__device__ int    g_flags[T_ * 128];              // grid-barrier flags

// ---------------------------------------------------------------------------
// Helpers
// ---------------------------------------------------------------------------
__device__ __forceinline__ uint32_t smem_u32(const void* p) {
    uint32_t a;
    asm("{ .reg .u64 t; cvta.to.shared.u64 t, %1; cvt.u32.u64 %0, t; }" : "=r"(a) : "l"(p));
    return a;
}
__device__ __forceinline__ uint32_t sw128(uint32_t off) { return off ^ ((off >> 3) & 0x70); }
__device__ __forceinline__ uint32_t sw64 (uint32_t off) { return off ^ ((off >> 3) & 0x30); }

#define CP16(dst, src) \
    asm volatile("cp.async.cg.shared.global [%0], [%1], 16;" :: "r"(dst), "l"(src))
#define CP_COMMIT() asm volatile("cp.async.commit_group;" ::: "memory")
#define CP_WAIT2()  asm volatile("cp.async.wait_group 2;" ::: "memory")
#define CP_WAIT1()  asm volatile("cp.async.wait_group 1;" ::: "memory")
#define CP_WAIT0()  asm volatile("cp.async.wait_group 0;" ::: "memory")

__device__ __forceinline__ void ldsm_x4(uint32_t* r, uint32_t addr) {
    asm volatile("ldmatrix.sync.aligned.m8n8.x4.shared.b16 {%0,%1,%2,%3}, [%4];"
                 : "=r"(r[0]), "=r"(r[1]), "=r"(r[2]), "=r"(r[3]) : "r"(addr));
}
__device__ __forceinline__ void ldsm_x2(uint32_t* r, uint32_t addr) {
    asm volatile("ldmatrix.sync.aligned.m8n8.x2.shared.b16 {%0,%1}, [%2];"
                 : "=r"(r[0]), "=r"(r[1]) : "r"(addr));
}
__device__ __forceinline__ void mma16816(float* c, const uint32_t* a, const uint32_t* b) {
    asm volatile(
        "mma.sync.aligned.m16n8k16.row.col.f32.f16.f16.f32 "
        "{%0,%1,%2,%3}, {%4,%5,%6,%7}, {%8,%9}, {%0,%1,%2,%3};"
        : "+f"(c[0]), "+f"(c[1]), "+f"(c[2]), "+f"(c[3])
        : "r"(a[0]), "r"(a[1]), "r"(a[2]), "r"(a[3]), "r"(b[0]), "r"(b[1]));
}

// ---------------------------------------------------------------------------
// Prep kernels
// ---------------------------------------------------------------------------
__global__ void init_state()
{
    int i = blockIdx.x * blockDim.x + threadIdx.x;
    if (i < B_ * U_) {
        __half z = __float2half(0.0f);
        g_h[0][i] = z;
        g_h[1][i] = z;
    }
    if (i < T_ * 128) g_flags[i] = 0;
}

__global__ void split_x(const float* __restrict__ x)
{
    size_t i = (size_t)blockIdx.x * blockDim.x + threadIdx.x;
    size_t n4 = (size_t)B_ * T_ * D_ / 4;
    if (i >= n4) return;
    float4 v = ((const float4*)x)[i];
    float vv[4] = {v.x, v.y, v.z, v.w};
    __half2* ph = (__half2*)g_xhi;
    __half2* pl = (__half2*)g_xlo;
    __half h[4], l[4];
    #pragma unroll
    for (int j = 0; j < 4; j++) {
        h[j] = __float2half_rn(vv[j]);
        l[j] = __float2half_rn(vv[j] - __half2float(h[j]));
    }
    ph[2*i]     = __halves2half2(h[0], h[1]);
    ph[2*i + 1] = __halves2half2(h[2], h[3]);
    pl[2*i]     = __halves2half2(l[0], l[1]);
    pl[2*i + 1] = __halves2half2(l[2], l[3]);
}

// src [rows][cols] fp32 -> Wt/Rt [cols][rows] single fp16 (device-resolved dst)
__global__ void transpose_h16_sel(const float* __restrict__ src,
                                  int which, int rows, int cols)
{
    __half* dst = which ? g_Rt : g_Wt;
    __shared__ float t[32][33];
    int x = blockIdx.x * 32 + threadIdx.x;
    int y0 = blockIdx.y * 32;
    #pragma unroll
    for (int i = 0; i < 32; i += 8)
        t[threadIdx.y + i][threadIdx.x] = src[(size_t)(y0 + threadIdx.y + i) * cols + x];
    __syncthreads();
    int ox = y0 + threadIdx.x;
    #pragma unroll
    for (int i = 0; i < 32; i += 8) {
        int orow = blockIdx.x * 32 + threadIdx.y + i;
        dst[(size_t)orow * rows + ox] = __float2half_rn(t[threadIdx.x][threadIdx.y + i]);
    }
}

// ---------------------------------------------------------------------------
// xz = x @ W + bias via mma.sync, fp16 2-term: Ah*B + Al*B — unchanged (R15)
// ---------------------------------------------------------------------------
#define XAHI 0
#define XALO 8192
#define XBHI 16384
#define XSTG 24576

__global__ __launch_bounds__(256) void gemm_xz_mma(const float* __restrict__ bias)
{
    extern __shared__ __align__(1024) char sm[];
    uint32_t smb = smem_u32(sm);
    const int tid  = threadIdx.x;
    const int wid  = tid >> 5;
    const int lane = tid & 31;
    const int m0 = blockIdx.y * 128;
    const int n0 = blockIdx.x * 128;

    const char* xh = (const char*)g_xhi;
    const char* xl = (const char*)g_xlo;
    const char* wh = (const char*)g_Wt;

    float acc[2][8][4] = {};

    auto issue = [&](int kc, int s) {
        uint32_t st = smb + s * XSTG;
        #pragma unroll
        for (int i = 0; i < 2; i++) {
            int idx = tid + 256 * i;
            int r = idx >> 2, g = idx & 3;
            CP16(st + XAHI + sw64(r * 64 + g * 16),
                 xh + (size_t)(m0 + r) * 1024 + kc * 64 + g * 16);
        }
        #pragma unroll
        for (int i = 0; i < 2; i++) {
            int idx = tid + 256 * i;
            int r = idx >> 2, g = idx & 3;
            CP16(st + XALO + sw64(r * 64 + g * 16),
                 xl + (size_t)(m0 + r) * 1024 + kc * 64 + g * 16);
        }
        #pragma unroll
        for (int i = 0; i < 2; i++) {
            int idx = tid + 256 * i;
            int r = idx >> 2, g = idx & 3;
            CP16(st + XBHI + sw64(r * 64 + g * 16),
                 wh + (size_t)(n0 + r) * 1024 + kc * 64 + g * 16);
        }
    };

    issue(0, 0); CP_COMMIT();

    const int mrow = 32 * (wid >> 1);
    const int ncol = 64 * (wid & 1);
    const int mi  = lane >> 3;
    const int mr  = lane & 7;
    const int rr  = lane & 15;

    for (int kc = 0; kc < 16; kc++) {
        int s = kc & 1;
        if (kc + 1 < 16) { issue(kc + 1, s ^ 1); CP_COMMIT(); CP_WAIT1(); }
        else             { CP_WAIT0(); }
        __syncthreads();

        uint32_t st = smb + s * XSTG;
        #pragma unroll
        for (int ks = 0; ks < 2; ks++) {
            uint32_t ah[2][4], al[2][4];
            #pragma unroll
            for (int mf = 0; mf < 2; mf++) {
                int row = mrow + 16 * mf + ((mi & 1) << 3) + mr;
                uint32_t off = row * 64 + ks * 32 + ((mi >> 1) << 4);
                ldsm_x4(ah[mf], st + XAHI + sw64(off));
                ldsm_x4(al[mf], st + XALO + sw64(off));
            }
            #pragma unroll
            for (int nf = 0; nf < 8; nf++) {
                uint32_t bh[2];
                int brow = ncol + 8 * nf + (rr & 7);
                uint32_t boff = brow * 64 + ks * 32 + ((rr >> 3) << 4);
                ldsm_x2(bh, st + XBHI + sw64(boff));
                #pragma unroll
                for (int mf = 0; mf < 2; mf++) {
                    mma16816(acc[mf][nf], ah[mf], bh);
                    mma16816(acc[mf][nf], al[mf], bh);
                }
            }
        }
        __syncthreads();
    }

    #pragma unroll
    for (int nf = 0; nf < 8; nf++) {
        int colg = n0 + ncol + 8 * nf + 2 * (lane & 3);
        float2 bv = *(const float2*)(bias + colg);
        #pragma unroll
        for (int mf = 0; mf < 2; mf++) {
            int rowg = m0 + mrow + 16 * mf + (lane >> 2);
            float2 o0 = make_float2(acc[mf][nf][0] + bv.x, acc[mf][nf][1] + bv.y);
            float2 o1 = make_float2(acc[mf][nf][2] + bv.x, acc[mf][nf][3] + bv.y);
            *(float2*)(g_xz + (size_t)rowg * G_ + colg)       = o0;
            *(float2*)(g_xz + (size_t)(rowg + 8) * G_ + colg) = o1;
        }
    }
}

// ---------------------------------------------------------------------------
// Persistent LSTM scan, fp16 1-term. Grid = 128 blocks (1/SM), 128 threads.
// Block owns 32 z-cols (8 u x 4 gates). R slice (64 KB fp16) smem-resident
// for all 512 steps; c in registers; h streams via 4-stage cp.async ring.
// B-operand ldsm via x4 pair loads (2 gate frags / instr).
// Cross-step sync: per-step flag array + acquire polling.
// SMEM: R 16 chunks x 4KB = 64K | h ring 4 x 8KB = 32K  -> 96 KB dynamic.
// ---------------------------------------------------------------------------
#define PR    0
#define PH    65536
#define PHSTG 8192
#define PSMEM 98304

__global__ __launch_bounds__(128) void lstm_scan(float* __restrict__ out)
{
    extern __shared__ __align__(1024) char sm[];
    uint32_t smb = smem_u32(sm);
    const int tid  = threadIdx.x;
    const int wid  = tid >> 5;
    const int lane = tid & 31;
    const int bid  = blockIdx.x;
    const int u0   = bid * 8;

    // ---- Load resident R slice once: 16 chunks x (32 rows x 128B) ----
    {
        const char* rp = (const char*)g_Rt;
        #pragma unroll 4
        for (int i = 0; i < 32; i++) {
            int idx = tid + 128 * i;               // 0..4095 granules
            int kc = idx >> 8;
            int j  = idx & 255;
            int c  = j >> 3, g = j & 7;
            int n  = ((c >> 3) << 10) + u0 + (c & 7);      // gate*1024 + u
            CP16(smb + PR + kc * 4096 + sw128(c * 128 + g * 16),
                 rp + (size_t)n * 2048 + (size_t)kc * 128 + g * 16);
        }
        CP_COMMIT(); CP_WAIT0();
        __syncthreads();
    }

    // ---- Per-thread mapping ----
    const int b0 = 16 * wid + (lane >> 2);
    const int uu = u0 + 2 * (lane & 3);
    const int mi = lane >> 3;
    const int mr = lane & 7;
    float c_reg[4] = {0.f, 0.f, 0.f, 0.f};   // [half*2 + j]

    for (int t = 0; t < T_; t++) {
        const char* hp = (const char*)g_h[t & 1];

        auto issue_h = [&](int kc) {
            uint32_t st = smb + PH + (kc & 3) * PHSTG;
            #pragma unroll
            for (int i = 0; i < 4; i++) {          // 64 rows x 8 granules
                int idx = tid + 128 * i;
                int r = idx >> 3, g = idx & 7;
                CP16(st + sw128(r * 128 + g * 16),
                     hp + (size_t)r * 2048 + (size_t)kc * 128 + g * 16);
            }
            CP_COMMIT();
        };

        issue_h(0); issue_h(1); issue_h(2);

        // xz prefetch for this step (overlaps ring fill)
        float2 xzr[2][4];
        #pragma unroll
        for (int half = 0; half < 2; half++) {
            size_t xb = ((size_t)(b0 + 8 * half) * T_ + t) * G_ + uu;
            #pragma unroll
            for (int f = 0; f < 4; f++)
                xzr[half][f] = __ldg((const float2*)(g_xz + xb + f * U_));
        }

        float acc[4][4] = {};   // [gate][frag]

        #pragma unroll 1
        for (int kc = 0; kc < 16; kc++) {
            if (kc <= 13)      { CP_WAIT2(); }
            else if (kc == 14) { CP_WAIT1(); }
            else               { CP_WAIT0(); }
            __syncthreads();

            uint32_t hst = smb + PH + (kc & 3) * PHSTG;
            uint32_t rbs = smb + PR + kc * 4096;
            #pragma unroll
            for (int ks = 0; ks < 4; ks++) {
                uint32_t ah[4];
                int row = 16 * wid + ((mi & 1) << 3) + mr;
                ldsm_x4(ah, hst + sw128(row * 128 + ks * 32 + ((mi >> 1) << 4)));
                #pragma unroll
                for (int fp = 0; fp < 2; fp++) {   // gate pairs {0,1},{2,3}
                    int f = 2 * fp;
                    uint32_t bb[4];
                    int brow = 8 * (f + (mi >> 1)) + mr;
                    uint32_t boff = brow * 128 + ks * 32 + ((mi & 1) << 4);
                    ldsm_x4(bb, rbs + sw128(boff));
                    mma16816(acc[f],     ah, bb);
                    mma16816(acc[f + 1], ah, bb + 2);
                }
            }
            if (kc + 3 < 16) issue_h(kc + 3);      // stage (kc-1)&3: read done
        }

        // ---- Gate fusion + state update (c in registers) ----
        __half* nh = g_h[(t + 1) & 1];
        #pragma unroll
        for (int half = 0; half < 2; half++) {
            int b = b0 + 8 * half;
            float hv[2];
            #pragma unroll
            for (int j = 0; j < 2; j++) {
                int a = 2 * half + j;
                float zi = acc[0][a] + (j ? xzr[half][0].y : xzr[half][0].x);
                float zf = acc[1][a] + (j ? xzr[half][1].y : xzr[half][1].x);
                float zc = acc[2][a] + (j ? xzr[half][2].y : xzr[half][2].x);
                float zo = acc[3][a] + (j ? xzr[half][3].y : xzr[half][3].x);
                float ig = 1.0f / (1.0f + __expf(-zi));
                float fg = 1.0f / (1.0f + __expf(-zf));
                float og = 1.0f / (1.0f + __expf(-zo));
                float cn = fg * c_reg[a] + ig * tanhf(zc);
                c_reg[a] = cn;
                hv[j] = og * tanhf(cn);
            }
            if (t == T_ - 1) {
                *(float2*)(out + b * U_ + uu) = make_float2(hv[0], hv[1]);
            } else {
                *(__half2*)(nh + b * U_ + uu) =
                    __halves2half2(__float2half_rn(hv[0]), __float2half_rn(hv[1]));
            }
        }

        // ---- Grid barrier: publish our h slice, wait for all 128 blocks ----
        if (t < T_ - 1) {
            __syncthreads();                     // all h writes of this block done
            if (tid == 0) {
                __threadfence();                 // make them visible gpu-wide
                asm volatile("st.release.gpu.global.u32 [%0], %1;"
                             :: "l"(g_flags + t * 128 + bid), "r"(1) : "memory");
            }
            if (tid < 32) {
                const int* fl = g_flags + t * 128 + lane * 4;
                uint4 v;
                while (true) {
                    asm volatile("ld.acquire.gpu.global.v4.u32 {%0,%1,%2,%3}, [%4];"
                                 : "=r"(v.x), "=r"(v.y), "=r"(v.z), "=r"(v.w)
                                 : "l"(fl));
                    if (v.x & v.y & v.z & v.w) break;
                    __nanosleep(30);
                }
            }
            __syncthreads();                     // barrier result visible block-wide
        }
    }
}

// ---------------------------------------------------------------------------
extern "C" void kernel_launch(void* const* d_in, const int* in_sizes, int n_in,
                              void* d_out, int out_size)
{
    const float* x    = (const float*)d_in[0];   // [64, 512, 512]
    const float* W    = (const float*)d_in[1];   // [512, 4096]
    const float* R    = (const float*)d_in[2];   // [1024, 4096]
    const float* bias = (const float*)d_in[3];   // [4096]
    float* out = (float*)d_out;                  // [64, 1024]

    cudaFuncSetAttribute(gemm_xz_mma,
                         cudaFuncAttributeMaxDynamicSharedMemorySize, 2 * XSTG);
    cudaFuncSetAttribute(lstm_scan,
                         cudaFuncAttributeMaxDynamicSharedMemorySize, PSMEM);

    init_state<<<256, 256>>>();
    split_x<<<(B_ * T_ * D_ / 4 + 255) / 256, 256>>>(x);
    transpose_h16_sel<<<dim3(G_ / 32, D_ / 32), dim3(32, 8)>>>(W, 0, D_, G_);
    transpose_h16_sel<<<dim3(G_ / 32, U_ / 32), dim3(32, 8)>>>(R, 1, U_, G_);
    gemm_xz_mma<<<dim3(G_ / 128, (B_ * T_) / 128), 256, 2 * XSTG>>>(bias);
    lstm_scan<<<128, 128, PSMEM>>>(out);
}